// round 13
// baseline (speedup 1.0000x reference)
#include <cuda_runtime.h>
#include <cuda.h>
#include <cuda_bf16.h>
#include <cstdint>

// ---------------------------------------------------------------------------
// Problem dims
// ---------------------------------------------------------------------------
#define M_TOTAL 8192
#define N_TOTAL 4096
#define K_TOTAL 4096

// Hybrid GEMM v6: additive law (validated R7/R11/R12):
//   T_kiter = tensor_server(61.7 cyc/col) + dp4a_issue(~36 cyc/col)
// -> shift columns to dp4a. 96 tensor cols (6 warps, 64x32) +
//    160 dp4a cols (8 warps, 32x80). 448 threads raises reg ceiling to 144.
#define BM 128
#define BN 256
#define BK 128
#define STAGES 4
#define KITERS (K_TOTAL / BK)       // 32

#define BN_T 96                     // tensor columns  N[0,96)
#define NTHREADS 448                // 6 tensor warps + 8 dp4a warps

#define A_STAGE (BM * BK)           // 16384 B
#define B_STAGE (BN * BK)           // 32768 B
#define CTRL_BYTES 1024
#define SMEM_A0 CTRL_BYTES
#define SMEM_B0 (SMEM_A0 + STAGES * A_STAGE)
#define SMEM_TOTAL (SMEM_B0 + STAGES * B_STAGE)   // 197632 B
#define STAGE_TX (A_STAGE + B_STAGE)              // 49152

// ---------------------------------------------------------------------------
// Device scratch
// ---------------------------------------------------------------------------
__device__ __align__(1024) int8_t g_xq[(size_t)M_TOTAL * K_TOTAL]; // [M][K]
__device__ __align__(1024) int8_t g_kq[(size_t)N_TOTAL * K_TOTAL]; // [N][K] (W^T)
__device__ float g_sx[M_TOTAL];
__device__ float g_sk[N_TOTAL];
__device__ float g_kpart[16 * N_TOTAL];

// ---------------------------------------------------------------------------
// Helpers
// ---------------------------------------------------------------------------
__device__ __forceinline__ uint32_t smem_u32(const void* p) {
    uint32_t a;
    asm("{ .reg .u64 t; cvta.to.shared.u64 t, %1; cvt.u32.u64 %0, t; }" : "=r"(a) : "l"(p));
    return a;
}
__device__ __forceinline__ void mbar_init(uint32_t a, uint32_t cnt) {
    asm volatile("mbarrier.init.shared.b64 [%0], %1;" :: "r"(a), "r"(cnt) : "memory");
}
__device__ __forceinline__ void mbar_expect_tx(uint32_t a, uint32_t bytes) {
    asm volatile("mbarrier.arrive.expect_tx.shared.b64 _, [%0], %1;" :: "r"(a), "r"(bytes) : "memory");
}
__device__ __forceinline__ void mbar_wait(uint32_t a, uint32_t parity) {
    asm volatile(
        "{\n\t.reg .pred P;\n"
        "W%=:\n\t"
        "mbarrier.try_wait.parity.acquire.cta.shared::cta.b64 P, [%0], %1, 0x989680;\n\t"
        "@P bra.uni D%=;\n\t"
        "bra.uni W%=;\n"
        "D%=:\n\t}"
        :: "r"(a), "r"(parity) : "memory");
}
__device__ __forceinline__ void tma_2d(uint32_t dst, const void* map, int x, int y, uint32_t bar) {
    asm volatile(
        "cp.async.bulk.tensor.2d.shared::cta.global.tile.mbarrier::complete_tx::bytes "
        "[%0], [%1, {%2, %3}], [%4];"
        :: "r"(dst), "l"(map), "r"(x), "r"(y), "r"(bar) : "memory");
}
__device__ __forceinline__ void ldsm_x4(uint32_t* r, uint32_t addr) {
    asm volatile("ldmatrix.sync.aligned.m8n8.x4.shared.b16 {%0,%1,%2,%3}, [%4];"
                 : "=r"(r[0]), "=r"(r[1]), "=r"(r[2]), "=r"(r[3]) : "r"(addr));
}
__device__ __forceinline__ void mma_s8(int* d, const uint32_t* a, const uint32_t* b) {
    asm volatile(
        "mma.sync.aligned.m16n8k32.row.col.s32.s8.s8.s32 "
        "{%0,%1,%2,%3}, {%4,%5,%6,%7}, {%8,%9}, {%0,%1,%2,%3};"
        : "+r"(d[0]), "+r"(d[1]), "+r"(d[2]), "+r"(d[3])
        : "r"(a[0]), "r"(a[1]), "r"(a[2]), "r"(a[3]), "r"(b[0]), "r"(b[1]));
}
__device__ __forceinline__ void lds128(uint32_t* r, uint32_t addr) {
    asm volatile("ld.shared.v4.u32 {%0,%1,%2,%3}, [%4];"
                 : "=r"(r[0]), "=r"(r[1]), "=r"(r[2]), "=r"(r[3]) : "r"(addr));
}
__device__ __forceinline__ int dp4a_s32(uint32_t a, uint32_t b, int c) {
    int d;
    asm("dp4a.s32.s32 %0, %1, %2, %3;" : "=r"(d) : "r"(a), "r"(b), "r"(c));
    return d;
}

// ---------------------------------------------------------------------------
// Pre-pass 1: per-row dynamic int8 quant of X -> g_xq, g_sx
// ---------------------------------------------------------------------------
__global__ void quant_x_kernel(const float* __restrict__ x) {
    const int m = blockIdx.x;
    const int t = threadIdx.x;  // 256 threads
    const float4* row = reinterpret_cast<const float4*>(x + (size_t)m * K_TOTAL);
    float4 v[4];
    float amax = 0.f;
#pragma unroll
    for (int i = 0; i < 4; i++) {
        v[i] = row[t + i * 256];
        amax = fmaxf(amax, fmaxf(fmaxf(fabsf(v[i].x), fabsf(v[i].y)),
                                 fmaxf(fabsf(v[i].z), fabsf(v[i].w))));
    }
#pragma unroll
    for (int o = 16; o > 0; o >>= 1) amax = fmaxf(amax, __shfl_xor_sync(0xffffffffu, amax, o));
    __shared__ float red[8];
    __shared__ float s_scale;
    if ((t & 31) == 0) red[t >> 5] = amax;
    __syncthreads();
    if (t < 32) {
        float a = (t < 8) ? red[t] : 0.f;
#pragma unroll
        for (int o = 4; o > 0; o >>= 1) a = fmaxf(a, __shfl_xor_sync(0xffffffffu, a, o));
        if (t == 0) {
            float s = fmaxf(a, 1e-6f) / 127.0f;
            s_scale = s;
            g_sx[m] = s;
        }
    }
    __syncthreads();
    const float inv = 1.0f / s_scale;
    uint32_t* outp = reinterpret_cast<uint32_t*>(g_xq + (size_t)m * K_TOTAL);
#pragma unroll
    for (int i = 0; i < 4; i++) {
        int q0 = (int)fminf(fmaxf(rintf(v[i].x * inv), -127.f), 127.f);
        int q1 = (int)fminf(fmaxf(rintf(v[i].y * inv), -127.f), 127.f);
        int q2 = (int)fminf(fmaxf(rintf(v[i].z * inv), -127.f), 127.f);
        int q3 = (int)fminf(fmaxf(rintf(v[i].w * inv), -127.f), 127.f);
        outp[t + i * 256] = (uint32_t)(q0 & 0xFF) | ((uint32_t)(q1 & 0xFF) << 8) |
                            ((uint32_t)(q2 & 0xFF) << 16) | ((uint32_t)q3 << 24);
    }
}

// ---------------------------------------------------------------------------
// Pre-pass 2: partial column amax of W [K, N]
// ---------------------------------------------------------------------------
__global__ void k_amax_partial_kernel(const float* __restrict__ kern) {
    const int f = blockIdx.x * 256 + threadIdx.x;
    const int d0 = blockIdx.y * 256;
    float a = 0.f;
#pragma unroll 4
    for (int d = d0; d < d0 + 256; d++)
        a = fmaxf(a, fabsf(kern[(size_t)d * N_TOTAL + f]));
    g_kpart[blockIdx.y * N_TOTAL + f] = a;
}

// ---------------------------------------------------------------------------
// Pre-pass 3: reduce partials -> sk, quantize W, transpose to [N][K] int8
// ---------------------------------------------------------------------------
__global__ void k_quant_fused_kernel(const float* __restrict__ kern) {
    __shared__ float tile[32][33];
    __shared__ float s_inv[32];
    const int f0 = blockIdx.x * 32;
    const int d0 = blockIdx.y * 32;
    const int tx = threadIdx.x, ty = threadIdx.y;  // (32, 8)
    if (ty == 0) {
        float a = 0.f;
#pragma unroll
        for (int p = 0; p < 16; p++) a = fmaxf(a, g_kpart[p * N_TOTAL + f0 + tx]);
        float s = fmaxf(a, 1e-6f) / 127.0f;
        s_inv[tx] = 1.0f / s;
        if (blockIdx.y == 0) g_sk[f0 + tx] = s;
    }
    __syncthreads();
    const float inv = s_inv[tx];
#pragma unroll
    for (int r = 0; r < 32; r += 8) {
        float q = fminf(fmaxf(rintf(kern[(size_t)(d0 + ty + r) * N_TOTAL + (f0 + tx)] * inv),
                              -127.f), 127.f);
        tile[ty + r][tx] = q;
    }
    __syncthreads();
#pragma unroll
    for (int r = 0; r < 32; r += 8) {
        g_kq[(size_t)(f0 + ty + r) * K_TOTAL + (d0 + tx)] = (int8_t)tile[tx][ty + r];
    }
}

// ---------------------------------------------------------------------------
// Hybrid GEMM v6: warps 0-5 IMMA over N[0,96) (64x32 tiles);
//                 warps 6-13 dp4a over N[96,256) (32x80 tiles)
// ---------------------------------------------------------------------------
__global__ void __launch_bounds__(NTHREADS, 1) gemm_s8_kernel(
    const __grid_constant__ CUtensorMap tmap_a,
    const __grid_constant__ CUtensorMap tmap_b,
    float* __restrict__ out)
{
    extern __shared__ char smem[];
    const uint32_t sb = smem_u32(smem);

    const int tid = threadIdx.x;
    const int wid = tid >> 5;
    const int lane = tid & 31;
    const int n0 = blockIdx.x * BN;
    const int m0 = blockIdx.y * BM;

    if (tid == 0) {
#pragma unroll
        for (int s = 0; s < STAGES; s++) mbar_init(sb + s * 16, 1);
    }
    __syncthreads();

    if (tid == 0) {
#pragma unroll
        for (int p = 0; p < STAGES - 1; p++) {
            mbar_expect_tx(sb + p * 16, STAGE_TX);
            tma_2d(sb + SMEM_A0 + p * A_STAGE, &tmap_a, p * BK, m0, sb + p * 16);
            tma_2d(sb + SMEM_B0 + p * B_STAGE, &tmap_b, p * BK, n0, sb + p * 16);
        }
    }

    // ---- tensor-warp state (wid 0..5): warp tile 64x32 over N[0,96) ----
    const int warp_m = wid & 1;
    const int warp_n = wid >> 1;         // 0..2 -> 32 cols each
    const int arow = warp_m * 64 + ((lane >> 3) & 1) * 8 + (lane & 7);
    const int acsel = (lane >> 4) & 1;
    const int brow = warp_n * 32 + ((lane >> 4) & 1) * 8 + (lane & 7);
    const int bcsel = (lane >> 3) & 1;
    const int swl = lane & 7;
    // XOR identity: ((2w+sel)^swl)<<4 == ((sel^swl)<<4) ^ (w<<5)
    uint32_t aAddr0[4], bAddr0[2];
#pragma unroll
    for (int mb = 0; mb < 4; mb++)
        aAddr0[mb] = (uint32_t)(arow + mb * 16) * BK + (uint32_t)((acsel ^ swl) << 4);
#pragma unroll
    for (int g = 0; g < 2; g++)
        bAddr0[g] = (uint32_t)(brow + g * 16) * BK + (uint32_t)((bcsel ^ swl) << 4);

    int acc[4][4][4];
#pragma unroll
    for (int mb = 0; mb < 4; mb++)
#pragma unroll
        for (int nb = 0; nb < 4; nb++)
#pragma unroll
            for (int r = 0; r < 4; r++) acc[mb][nb][r] = 0;

    // ---- dp4a-warp state (wid 6..13): warp tile 32x80 over N[96,256) ----
    const int widD = wid - 6;            // 0..7
    const int wmD = widD & 3;            // 4 row-groups of 32
    const int wnD = widD >> 2;           // 2 col-groups of 80
    const int tmD = lane >> 3;           // 0..3
    const int tnD = lane & 7;            // 0..7
    uint32_t aOff[8], bOff[10];
#pragma unroll
    for (int i = 0; i < 8; i++) {
        int m = wmD * 32 + tmD + 4 * i;
        aOff[i] = (uint32_t)m * BK + (uint32_t)((m & 7) << 4);
    }
#pragma unroll
    for (int j = 0; j < 10; j++) {
        int n = BN_T + wnD * 80 + tnD + 8 * j;   // 96, 80 both %8==0 -> n&7==tnD
        bOff[j] = (uint32_t)n * BK + (uint32_t)((n & 7) << 4);
    }
    int accD[8][10];
#pragma unroll
    for (int i = 0; i < 8; i++)
#pragma unroll
        for (int j = 0; j < 10; j++) accD[i][j] = 0;

    for (int kt = 0; kt < KITERS; kt++) {
        if (tid == 0 && kt + STAGES - 1 < KITERS) {
            const int ps = (kt + STAGES - 1) & (STAGES - 1);
            mbar_expect_tx(sb + ps * 16, STAGE_TX);
            tma_2d(sb + SMEM_A0 + ps * A_STAGE, &tmap_a, (kt + STAGES - 1) * BK, m0,
                   sb + ps * 16);
            tma_2d(sb + SMEM_B0 + ps * B_STAGE, &tmap_b, (kt + STAGES - 1) * BK, n0,
                   sb + ps * 16);
        }

        const int st = kt & (STAGES - 1);
        mbar_wait(sb + st * 16, (kt >> 2) & 1);

        const uint32_t aSt = sb + SMEM_A0 + st * A_STAGE;
        const uint32_t bSt = sb + SMEM_B0 + st * B_STAGE;

        if (tid < 192) {
            // -------- IMMA path: 4 x k32 steps, 64x32 per warp --------
#pragma unroll
            for (int w = 0; w < 4; w++) {
                uint32_t afr[4][4], bfr[4][2];
#pragma unroll
                for (int mb = 0; mb < 4; mb++)
                    ldsm_x4(afr[mb], (aSt + aAddr0[mb]) ^ (uint32_t)(w << 5));
#pragma unroll
                for (int g = 0; g < 2; g++) {
                    uint32_t r[4];
                    ldsm_x4(r, (bSt + bAddr0[g]) ^ (uint32_t)(w << 5));
                    bfr[2 * g][0] = r[0]; bfr[2 * g][1] = r[1];
                    bfr[2 * g + 1][0] = r[2]; bfr[2 * g + 1][1] = r[3];
                }
#pragma unroll
                for (int mb = 0; mb < 4; mb++)
#pragma unroll
                    for (int nb = 0; nb < 4; nb++)
                        mma_s8(acc[mb][nb], afr[mb], bfr[nb]);
            }
        } else {
            // -------- dp4a path: lds128 operands, 8 x k16 chunks, 32x80 ------
#pragma unroll
            for (int c = 0; c < 8; c++) {
                uint32_t av[8][4];
#pragma unroll
                for (int i = 0; i < 8; i++)
                    lds128(av[i], (aSt + aOff[i]) ^ (uint32_t)(c << 4));
#pragma unroll
                for (int jj = 0; jj < 5; jj++) {
                    uint32_t bv[2][4];
#pragma unroll
                    for (int j2 = 0; j2 < 2; j2++)
                        lds128(bv[j2], (bSt + bOff[jj * 2 + j2]) ^ (uint32_t)(c << 4));
#pragma unroll
                    for (int i = 0; i < 8; i++)
#pragma unroll
                        for (int j2 = 0; j2 < 2; j2++)
#pragma unroll
                            for (int w = 0; w < 4; w++)
                                accD[i][jj * 2 + j2] =
                                    dp4a_s32(av[i][w], bv[j2][w], accD[i][jj * 2 + j2]);
                }
            }
        }

        __syncthreads();   // release stage st for the producer
    }

    // ---------------- Epilogue ----------------
    if (tid < 192) {
        const int qid = lane >> 2;
        const int qtid = lane & 3;
#pragma unroll
        for (int mb = 0; mb < 4; mb++) {
            const int mlo = m0 + warp_m * 64 + mb * 16 + qid;
            const float sx0 = g_sx[mlo];
            const float sx1 = g_sx[mlo + 8];
            float* orow0 = out + (size_t)mlo * N_TOTAL + n0;
            float* orow1 = out + (size_t)(mlo + 8) * N_TOTAL + n0;
#pragma unroll
            for (int nb = 0; nb < 4; nb++) {
                const int n = warp_n * 32 + nb * 8 + qtid * 2;
                const float k0v = g_sk[n0 + n], k1v = g_sk[n0 + n + 1];
                float2 r0, r1;
                r0.x = (float)acc[mb][nb][0] * sx0 * k0v;
                r0.y = (float)acc[mb][nb][1] * sx0 * k1v;
                r1.x = (float)acc[mb][nb][2] * sx1 * k0v;
                r1.y = (float)acc[mb][nb][3] * sx1 * k1v;
                *reinterpret_cast<float2*>(orow0 + n) = r0;
                *reinterpret_cast<float2*>(orow1 + n) = r1;
            }
        }
    } else {
#pragma unroll
        for (int i = 0; i < 8; i++) {
            const int m = m0 + wmD * 32 + tmD + 4 * i;
            const float sx = g_sx[m];
            float* orow = out + (size_t)m * N_TOTAL + n0;
#pragma unroll
            for (int j = 0; j < 10; j++) {
                const int n = BN_T + wnD * 80 + tnD + 8 * j;
                orow[n] = (float)accD[i][j] * sx * g_sk[n0 + n];
            }
        }
    }
}

// ---------------------------------------------------------------------------
// Launch (GEMM at global launch index 5 so ncu -s 5 profiles it)
// ---------------------------------------------------------------------------
typedef CUresult (*PFN_encode_t)(CUtensorMap*, CUtensorMapDataType, cuuint32_t, void*,
                                 const cuuint64_t*, const cuuint64_t*, const cuuint32_t*,
                                 const cuuint32_t*, CUtensorMapInterleave, CUtensorMapSwizzle,
                                 CUtensorMapL2promotion, CUtensorMapFloatOOBfill);

extern "C" void kernel_launch(void* const* d_in, const int* in_sizes, int n_in,
                              void* d_out, int out_size) {
    const float* x = (const float*)d_in[0];
    const float* kern = (const float*)d_in[1];
    if (n_in >= 2 && in_sizes[0] < in_sizes[1]) {
        const float* t = x; x = kern; kern = t;
    }
    float* out = (float*)d_out;

    quant_x_kernel<<<M_TOTAL, 256>>>(x);
    k_amax_partial_kernel<<<dim3(N_TOTAL / 256, K_TOTAL / 256), 256>>>(kern);
    k_quant_fused_kernel<<<dim3(N_TOTAL / 32, K_TOTAL / 32), dim3(32, 8)>>>(kern);

    void* xq_ptr = nullptr;
    void* kq_ptr = nullptr;
    cudaGetSymbolAddress(&xq_ptr, g_xq);
    cudaGetSymbolAddress(&kq_ptr, g_kq);

    void* fnp = nullptr;
    cudaDriverEntryPointQueryResult qr;
    cudaGetDriverEntryPointByVersion("cuTensorMapEncodeTiled", &fnp, 12000,
                                     cudaEnableDefault, &qr);
    PFN_encode_t encode = (PFN_encode_t)fnp;

    CUtensorMap tA, tB;
    {
        cuuint64_t dims[2] = {K_TOTAL, M_TOTAL};
        cuuint64_t str[1] = {K_TOTAL};
        cuuint32_t box[2] = {BK, BM};
        cuuint32_t es[2] = {1, 1};
        encode(&tA, CU_TENSOR_MAP_DATA_TYPE_UINT8, 2, xq_ptr, dims, str, box, es,
               CU_TENSOR_MAP_INTERLEAVE_NONE, CU_TENSOR_MAP_SWIZZLE_128B,
               CU_TENSOR_MAP_L2_PROMOTION_L2_128B, CU_TENSOR_MAP_FLOAT_OOB_FILL_NONE);
    }
    {
        cuuint64_t dims[2] = {K_TOTAL, N_TOTAL};
        cuuint64_t str[1] = {K_TOTAL};
        cuuint32_t box[2] = {BK, BN};
        cuuint32_t es[2] = {1, 1};
        encode(&tB, CU_TENSOR_MAP_DATA_TYPE_UINT8, 2, kq_ptr, dims, str, box, es,
               CU_TENSOR_MAP_INTERLEAVE_NONE, CU_TENSOR_MAP_SWIZZLE_128B,
               CU_TENSOR_MAP_L2_PROMOTION_L2_128B, CU_TENSOR_MAP_FLOAT_OOB_FILL_NONE);
    }

    cudaFuncSetAttribute(gemm_s8_kernel, cudaFuncAttributeMaxDynamicSharedMemorySize,
                         SMEM_TOTAL);
    gemm_s8_kernel<<<dim3(N_TOTAL / BN, M_TOTAL / BM), NTHREADS, SMEM_TOTAL>>>(tA, tB, out);
}

// round 14
// speedup vs baseline: 1.0627x; 1.0627x over previous
#include <cuda_runtime.h>
#include <cuda.h>
#include <cuda_bf16.h>
#include <cstdint>

// ---------------------------------------------------------------------------
// Problem dims
// ---------------------------------------------------------------------------
#define M_TOTAL 8192
#define N_TOTAL 4096
#define K_TOTAL 4096

// Hybrid GEMM v7: additive law optimum 96/160, spill-free this time.
// R13 failed because 8 dp4a warps x 80 accs/thread spilled (128-reg ceiling).
// Fix: 10 dp4a warps x 64 accs/thread (exact R10 register shape).
//   warps 0-5  : IMMA, 64x32 tiles, N[0,96)
//   warps 6-15 : dp4a, 64x32 tiles (2 row-groups x 5 col-groups), N[96,256)
#define BM 128
#define BN 256
#define BK 128
#define STAGES 4
#define KITERS (K_TOTAL / BK)       // 32

#define BN_T 96                     // tensor columns  N[0,96)
#define NTHREADS 512                // 6 tensor warps + 10 dp4a warps

#define A_STAGE (BM * BK)           // 16384 B
#define B_STAGE (BN * BK)           // 32768 B
#define CTRL_BYTES 1024
#define SMEM_A0 CTRL_BYTES
#define SMEM_B0 (SMEM_A0 + STAGES * A_STAGE)
#define SMEM_TOTAL (SMEM_B0 + STAGES * B_STAGE)   // 197632 B
#define STAGE_TX (A_STAGE + B_STAGE)              // 49152

// ---------------------------------------------------------------------------
// Device scratch
// ---------------------------------------------------------------------------
__device__ __align__(1024) int8_t g_xq[(size_t)M_TOTAL * K_TOTAL]; // [M][K]
__device__ __align__(1024) int8_t g_kq[(size_t)N_TOTAL * K_TOTAL]; // [N][K] (W^T)
__device__ float g_sx[M_TOTAL];
__device__ float g_sk[N_TOTAL];
__device__ float g_kpart[16 * N_TOTAL];

// ---------------------------------------------------------------------------
// Helpers
// ---------------------------------------------------------------------------
__device__ __forceinline__ uint32_t smem_u32(const void* p) {
    uint32_t a;
    asm("{ .reg .u64 t; cvta.to.shared.u64 t, %1; cvt.u32.u64 %0, t; }" : "=r"(a) : "l"(p));
    return a;
}
__device__ __forceinline__ void mbar_init(uint32_t a, uint32_t cnt) {
    asm volatile("mbarrier.init.shared.b64 [%0], %1;" :: "r"(a), "r"(cnt) : "memory");
}
__device__ __forceinline__ void mbar_expect_tx(uint32_t a, uint32_t bytes) {
    asm volatile("mbarrier.arrive.expect_tx.shared.b64 _, [%0], %1;" :: "r"(a), "r"(bytes) : "memory");
}
__device__ __forceinline__ void mbar_wait(uint32_t a, uint32_t parity) {
    asm volatile(
        "{\n\t.reg .pred P;\n"
        "W%=:\n\t"
        "mbarrier.try_wait.parity.acquire.cta.shared::cta.b64 P, [%0], %1, 0x989680;\n\t"
        "@P bra.uni D%=;\n\t"
        "bra.uni W%=;\n"
        "D%=:\n\t}"
        :: "r"(a), "r"(parity) : "memory");
}
__device__ __forceinline__ void tma_2d(uint32_t dst, const void* map, int x, int y, uint32_t bar) {
    asm volatile(
        "cp.async.bulk.tensor.2d.shared::cta.global.tile.mbarrier::complete_tx::bytes "
        "[%0], [%1, {%2, %3}], [%4];"
        :: "r"(dst), "l"(map), "r"(x), "r"(y), "r"(bar) : "memory");
}
__device__ __forceinline__ void ldsm_x4(uint32_t* r, uint32_t addr) {
    asm volatile("ldmatrix.sync.aligned.m8n8.x4.shared.b16 {%0,%1,%2,%3}, [%4];"
                 : "=r"(r[0]), "=r"(r[1]), "=r"(r[2]), "=r"(r[3]) : "r"(addr));
}
__device__ __forceinline__ void mma_s8(int* d, const uint32_t* a, const uint32_t* b) {
    asm volatile(
        "mma.sync.aligned.m16n8k32.row.col.s32.s8.s8.s32 "
        "{%0,%1,%2,%3}, {%4,%5,%6,%7}, {%8,%9}, {%0,%1,%2,%3};"
        : "+r"(d[0]), "+r"(d[1]), "+r"(d[2]), "+r"(d[3])
        : "r"(a[0]), "r"(a[1]), "r"(a[2]), "r"(a[3]), "r"(b[0]), "r"(b[1]));
}
__device__ __forceinline__ void lds128(uint32_t* r, uint32_t addr) {
    asm volatile("ld.shared.v4.u32 {%0,%1,%2,%3}, [%4];"
                 : "=r"(r[0]), "=r"(r[1]), "=r"(r[2]), "=r"(r[3]) : "r"(addr));
}
__device__ __forceinline__ int dp4a_s32(uint32_t a, uint32_t b, int c) {
    int d;
    asm("dp4a.s32.s32 %0, %1, %2, %3;" : "=r"(d) : "r"(a), "r"(b), "r"(c));
    return d;
}

// ---------------------------------------------------------------------------
// Pre-pass 1: per-row dynamic int8 quant of X -> g_xq, g_sx
// ---------------------------------------------------------------------------
__global__ void quant_x_kernel(const float* __restrict__ x) {
    const int m = blockIdx.x;
    const int t = threadIdx.x;  // 256 threads
    const float4* row = reinterpret_cast<const float4*>(x + (size_t)m * K_TOTAL);
    float4 v[4];
    float amax = 0.f;
#pragma unroll
    for (int i = 0; i < 4; i++) {
        v[i] = row[t + i * 256];
        amax = fmaxf(amax, fmaxf(fmaxf(fabsf(v[i].x), fabsf(v[i].y)),
                                 fmaxf(fabsf(v[i].z), fabsf(v[i].w))));
    }
#pragma unroll
    for (int o = 16; o > 0; o >>= 1) amax = fmaxf(amax, __shfl_xor_sync(0xffffffffu, amax, o));
    __shared__ float red[8];
    __shared__ float s_scale;
    if ((t & 31) == 0) red[t >> 5] = amax;
    __syncthreads();
    if (t < 32) {
        float a = (t < 8) ? red[t] : 0.f;
#pragma unroll
        for (int o = 4; o > 0; o >>= 1) a = fmaxf(a, __shfl_xor_sync(0xffffffffu, a, o));
        if (t == 0) {
            float s = fmaxf(a, 1e-6f) / 127.0f;
            s_scale = s;
            g_sx[m] = s;
        }
    }
    __syncthreads();
    const float inv = 1.0f / s_scale;
    uint32_t* outp = reinterpret_cast<uint32_t*>(g_xq + (size_t)m * K_TOTAL);
#pragma unroll
    for (int i = 0; i < 4; i++) {
        int q0 = (int)fminf(fmaxf(rintf(v[i].x * inv), -127.f), 127.f);
        int q1 = (int)fminf(fmaxf(rintf(v[i].y * inv), -127.f), 127.f);
        int q2 = (int)fminf(fmaxf(rintf(v[i].z * inv), -127.f), 127.f);
        int q3 = (int)fminf(fmaxf(rintf(v[i].w * inv), -127.f), 127.f);
        outp[t + i * 256] = (uint32_t)(q0 & 0xFF) | ((uint32_t)(q1 & 0xFF) << 8) |
                            ((uint32_t)(q2 & 0xFF) << 16) | ((uint32_t)q3 << 24);
    }
}

// ---------------------------------------------------------------------------
// Pre-pass 2: partial column amax of W [K, N]
// ---------------------------------------------------------------------------
__global__ void k_amax_partial_kernel(const float* __restrict__ kern) {
    const int f = blockIdx.x * 256 + threadIdx.x;
    const int d0 = blockIdx.y * 256;
    float a = 0.f;
#pragma unroll 4
    for (int d = d0; d < d0 + 256; d++)
        a = fmaxf(a, fabsf(kern[(size_t)d * N_TOTAL + f]));
    g_kpart[blockIdx.y * N_TOTAL + f] = a;
}

// ---------------------------------------------------------------------------
// Pre-pass 3: reduce partials -> sk, quantize W, transpose to [N][K] int8
// ---------------------------------------------------------------------------
__global__ void k_quant_fused_kernel(const float* __restrict__ kern) {
    __shared__ float tile[32][33];
    __shared__ float s_inv[32];
    const int f0 = blockIdx.x * 32;
    const int d0 = blockIdx.y * 32;
    const int tx = threadIdx.x, ty = threadIdx.y;  // (32, 8)
    if (ty == 0) {
        float a = 0.f;
#pragma unroll
        for (int p = 0; p < 16; p++) a = fmaxf(a, g_kpart[p * N_TOTAL + f0 + tx]);
        float s = fmaxf(a, 1e-6f) / 127.0f;
        s_inv[tx] = 1.0f / s;
        if (blockIdx.y == 0) g_sk[f0 + tx] = s;
    }
    __syncthreads();
    const float inv = s_inv[tx];
#pragma unroll
    for (int r = 0; r < 32; r += 8) {
        float q = fminf(fmaxf(rintf(kern[(size_t)(d0 + ty + r) * N_TOTAL + (f0 + tx)] * inv),
                              -127.f), 127.f);
        tile[ty + r][tx] = q;
    }
    __syncthreads();
#pragma unroll
    for (int r = 0; r < 32; r += 8) {
        g_kq[(size_t)(f0 + ty + r) * K_TOTAL + (d0 + tx)] = (int8_t)tile[tx][ty + r];
    }
}

// ---------------------------------------------------------------------------
// Hybrid GEMM v7: warps 0-5 IMMA over N[0,96); warps 6-15 dp4a over N[96,256)
// ---------------------------------------------------------------------------
__global__ void __launch_bounds__(NTHREADS, 1) gemm_s8_kernel(
    const __grid_constant__ CUtensorMap tmap_a,
    const __grid_constant__ CUtensorMap tmap_b,
    float* __restrict__ out)
{
    extern __shared__ char smem[];
    const uint32_t sb = smem_u32(smem);

    const int tid = threadIdx.x;
    const int wid = tid >> 5;
    const int lane = tid & 31;
    const int n0 = blockIdx.x * BN;
    const int m0 = blockIdx.y * BM;

    if (tid == 0) {
#pragma unroll
        for (int s = 0; s < STAGES; s++) mbar_init(sb + s * 16, 1);
    }
    __syncthreads();

    if (tid == 0) {
#pragma unroll
        for (int p = 0; p < STAGES - 1; p++) {
            mbar_expect_tx(sb + p * 16, STAGE_TX);
            tma_2d(sb + SMEM_A0 + p * A_STAGE, &tmap_a, p * BK, m0, sb + p * 16);
            tma_2d(sb + SMEM_B0 + p * B_STAGE, &tmap_b, p * BK, n0, sb + p * 16);
        }
    }

    // ---- tensor-warp state (wid 0..5): warp tile 64x32 over N[0,96) ----
    const int warp_m = wid & 1;
    const int warp_n = wid >> 1;         // 0..2 -> 32 cols each
    const int arow = warp_m * 64 + ((lane >> 3) & 1) * 8 + (lane & 7);
    const int acsel = (lane >> 4) & 1;
    const int brow = warp_n * 32 + ((lane >> 4) & 1) * 8 + (lane & 7);
    const int bcsel = (lane >> 3) & 1;
    const int swl = lane & 7;
    // XOR identity: ((2w+sel)^swl)<<4 == ((sel^swl)<<4) ^ (w<<5)
    uint32_t aAddr0[4], bAddr0[2];
#pragma unroll
    for (int mb = 0; mb < 4; mb++)
        aAddr0[mb] = (uint32_t)(arow + mb * 16) * BK + (uint32_t)((acsel ^ swl) << 4);
#pragma unroll
    for (int g = 0; g < 2; g++)
        bAddr0[g] = (uint32_t)(brow + g * 16) * BK + (uint32_t)((bcsel ^ swl) << 4);

    int acc[4][4][4];
#pragma unroll
    for (int mb = 0; mb < 4; mb++)
#pragma unroll
        for (int nb = 0; nb < 4; nb++)
#pragma unroll
            for (int r = 0; r < 4; r++) acc[mb][nb][r] = 0;

    // ---- dp4a-warp state (wid 6..15): warp tile 64x32, 2x5 warp grid ------
    const int widD = wid - 6;            // 0..9
    const int wmD = widD / 5;            // 0..1 -> 64-row group
    const int wnD = widD % 5;            // 0..4 -> 32-col group
    const int tmD = lane >> 2;           // 0..7 (row lanes)
    const int tnD = lane & 3;            // 0..3 (col lanes)
    uint32_t aOff[8], bOff[8];
#pragma unroll
    for (int i = 0; i < 8; i++) {
        int m = wmD * 64 + tmD + 8 * i;  // m&7 == tmD
        aOff[i] = (uint32_t)m * BK + (uint32_t)((m & 7) << 4);
    }
#pragma unroll
    for (int j = 0; j < 8; j++) {
        int n = BN_T + wnD * 32 + tnD + 4 * j;   // n&7 = (tnD+4j)&7
        bOff[j] = (uint32_t)n * BK + (uint32_t)((n & 7) << 4);
    }
    int accD[8][8];
#pragma unroll
    for (int i = 0; i < 8; i++)
#pragma unroll
        for (int j = 0; j < 8; j++) accD[i][j] = 0;

    for (int kt = 0; kt < KITERS; kt++) {
        if (tid == 0 && kt + STAGES - 1 < KITERS) {
            const int ps = (kt + STAGES - 1) & (STAGES - 1);
            mbar_expect_tx(sb + ps * 16, STAGE_TX);
            tma_2d(sb + SMEM_A0 + ps * A_STAGE, &tmap_a, (kt + STAGES - 1) * BK, m0,
                   sb + ps * 16);
            tma_2d(sb + SMEM_B0 + ps * B_STAGE, &tmap_b, (kt + STAGES - 1) * BK, n0,
                   sb + ps * 16);
        }

        const int st = kt & (STAGES - 1);
        mbar_wait(sb + st * 16, (kt >> 2) & 1);

        const uint32_t aSt = sb + SMEM_A0 + st * A_STAGE;
        const uint32_t bSt = sb + SMEM_B0 + st * B_STAGE;

        if (tid < 192) {
            // -------- IMMA path: 4 x k32 steps, 64x32 per warp --------
#pragma unroll
            for (int w = 0; w < 4; w++) {
                uint32_t afr[4][4], bfr[4][2];
#pragma unroll
                for (int mb = 0; mb < 4; mb++)
                    ldsm_x4(afr[mb], (aSt + aAddr0[mb]) ^ (uint32_t)(w << 5));
#pragma unroll
                for (int g = 0; g < 2; g++) {
                    uint32_t r[4];
                    ldsm_x4(r, (bSt + bAddr0[g]) ^ (uint32_t)(w << 5));
                    bfr[2 * g][0] = r[0]; bfr[2 * g][1] = r[1];
                    bfr[2 * g + 1][0] = r[2]; bfr[2 * g + 1][1] = r[3];
                }
#pragma unroll
                for (int mb = 0; mb < 4; mb++)
#pragma unroll
                    for (int nb = 0; nb < 4; nb++)
                        mma_s8(acc[mb][nb], afr[mb], bfr[nb]);
            }
        } else {
            // -------- dp4a path: lds128 operands, 8 x k16 chunks, 64x32 ------
#pragma unroll
            for (int c = 0; c < 8; c++) {
                uint32_t av[8][4];
#pragma unroll
                for (int i = 0; i < 8; i++)
                    lds128(av[i], (aSt + aOff[i]) ^ (uint32_t)(c << 4));
#pragma unroll
                for (int jj = 0; jj < 2; jj++) {
                    uint32_t bv[4][4];
#pragma unroll
                    for (int j4 = 0; j4 < 4; j4++)
                        lds128(bv[j4], (bSt + bOff[jj * 4 + j4]) ^ (uint32_t)(c << 4));
#pragma unroll
                    for (int i = 0; i < 8; i++)
#pragma unroll
                        for (int j4 = 0; j4 < 4; j4++)
#pragma unroll
                            for (int w = 0; w < 4; w++)
                                accD[i][jj * 4 + j4] =
                                    dp4a_s32(av[i][w], bv[j4][w], accD[i][jj * 4 + j4]);
                }
            }
        }

        __syncthreads();   // release stage st for the producer
    }

    // ---------------- Epilogue ----------------
    if (tid < 192) {
        const int qid = lane >> 2;
        const int qtid = lane & 3;
#pragma unroll
        for (int mb = 0; mb < 4; mb++) {
            const int mlo = m0 + warp_m * 64 + mb * 16 + qid;
            const float sx0 = g_sx[mlo];
            const float sx1 = g_sx[mlo + 8];
            float* orow0 = out + (size_t)mlo * N_TOTAL + n0;
            float* orow1 = out + (size_t)(mlo + 8) * N_TOTAL + n0;
#pragma unroll
            for (int nb = 0; nb < 4; nb++) {
                const int n = warp_n * 32 + nb * 8 + qtid * 2;
                const float k0v = g_sk[n0 + n], k1v = g_sk[n0 + n + 1];
                float2 r0, r1;
                r0.x = (float)acc[mb][nb][0] * sx0 * k0v;
                r0.y = (float)acc[mb][nb][1] * sx0 * k1v;
                r1.x = (float)acc[mb][nb][2] * sx1 * k0v;
                r1.y = (float)acc[mb][nb][3] * sx1 * k1v;
                *reinterpret_cast<float2*>(orow0 + n) = r0;
                *reinterpret_cast<float2*>(orow1 + n) = r1;
            }
        }
    } else {
#pragma unroll
        for (int i = 0; i < 8; i++) {
            const int m = m0 + wmD * 64 + tmD + 8 * i;
            const float sx = g_sx[m];
            float* orow = out + (size_t)m * N_TOTAL + n0;
#pragma unroll
            for (int j = 0; j < 8; j++) {
                const int n = BN_T + wnD * 32 + tnD + 4 * j;
                orow[n] = (float)accD[i][j] * sx * g_sk[n0 + n];
            }
        }
    }
}

// ---------------------------------------------------------------------------
// Launch (GEMM at global launch index 5 so ncu -s 5 profiles it)
// ---------------------------------------------------------------------------
typedef CUresult (*PFN_encode_t)(CUtensorMap*, CUtensorMapDataType, cuuint32_t, void*,
                                 const cuuint64_t*, const cuuint64_t*, const cuuint32_t*,
                                 const cuuint32_t*, CUtensorMapInterleave, CUtensorMapSwizzle,
                                 CUtensorMapL2promotion, CUtensorMapFloatOOBfill);

extern "C" void kernel_launch(void* const* d_in, const int* in_sizes, int n_in,
                              void* d_out, int out_size) {
    const float* x = (const float*)d_in[0];
    const float* kern = (const float*)d_in[1];
    if (n_in >= 2 && in_sizes[0] < in_sizes[1]) {
        const float* t = x; x = kern; kern = t;
    }
    float* out = (float*)d_out;

    quant_x_kernel<<<M_TOTAL, 256>>>(x);
    k_amax_partial_kernel<<<dim3(N_TOTAL / 256, K_TOTAL / 256), 256>>>(kern);
    k_quant_fused_kernel<<<dim3(N_TOTAL / 32, K_TOTAL / 32), dim3(32, 8)>>>(kern);

    void* xq_ptr = nullptr;
    void* kq_ptr = nullptr;
    cudaGetSymbolAddress(&xq_ptr, g_xq);
    cudaGetSymbolAddress(&kq_ptr, g_kq);

    void* fnp = nullptr;
    cudaDriverEntryPointQueryResult qr;
    cudaGetDriverEntryPointByVersion("cuTensorMapEncodeTiled", &fnp, 12000,
                                     cudaEnableDefault, &qr);
    PFN_encode_t encode = (PFN_encode_t)fnp;

    CUtensorMap tA, tB;
    {
        cuuint64_t dims[2] = {K_TOTAL, M_TOTAL};
        cuuint64_t str[1] = {K_TOTAL};
        cuuint32_t box[2] = {BK, BM};
        cuuint32_t es[2] = {1, 1};
        encode(&tA, CU_TENSOR_MAP_DATA_TYPE_UINT8, 2, xq_ptr, dims, str, box, es,
               CU_TENSOR_MAP_INTERLEAVE_NONE, CU_TENSOR_MAP_SWIZZLE_128B,
               CU_TENSOR_MAP_L2_PROMOTION_L2_128B, CU_TENSOR_MAP_FLOAT_OOB_FILL_NONE);
    }
    {
        cuuint64_t dims[2] = {K_TOTAL, N_TOTAL};
        cuuint64_t str[1] = {K_TOTAL};
        cuuint32_t box[2] = {BK, BN};
        cuuint32_t es[2] = {1, 1};
        encode(&tB, CU_TENSOR_MAP_DATA_TYPE_UINT8, 2, kq_ptr, dims, str, box, es,
               CU_TENSOR_MAP_INTERLEAVE_NONE, CU_TENSOR_MAP_SWIZZLE_128B,
               CU_TENSOR_MAP_L2_PROMOTION_L2_128B, CU_TENSOR_MAP_FLOAT_OOB_FILL_NONE);
    }

    cudaFuncSetAttribute(gemm_s8_kernel, cudaFuncAttributeMaxDynamicSharedMemorySize,
                         SMEM_TOTAL);
    gemm_s8_kernel<<<dim3(N_TOTAL / BN, M_TOTAL / BM), NTHREADS, SMEM_TOTAL>>>(tA, tB, out);
}

// round 15
// speedup vs baseline: 1.3511x; 1.2714x over previous
#include <cuda_runtime.h>
#include <cuda.h>
#include <cuda_bf16.h>
#include <cstdint>

// ---------------------------------------------------------------------------
// Problem dims
// ---------------------------------------------------------------------------
#define M_TOTAL 8192
#define N_TOTAL 4096
#define K_TOTAL 4096

// Hybrid GEMM v8 = R10 (best: 1472us; 8 IMMA warps N[0,128) + 8 dp4a warps
// N[128,256), TMA, 4 stages, balanced 2+2 warps/SMSP) with dp4a A-operand
// addresses converted to compile-time immediate offsets (per-thread chunk
// order c = p ^ tmD), removing 64 LOP3/thread/kiter of address math.
#define BM 128
#define BN 256
#define BK 128
#define STAGES 4
#define KITERS (K_TOTAL / BK)       // 32

#define BN_T 128                    // tensor columns  N[0,128)
#define NTHREADS 512

#define A_STAGE (BM * BK)           // 16384 B
#define B_STAGE (BN * BK)           // 32768 B
#define CTRL_BYTES 1024
#define SMEM_A0 CTRL_BYTES
#define SMEM_B0 (SMEM_A0 + STAGES * A_STAGE)
#define SMEM_TOTAL (SMEM_B0 + STAGES * B_STAGE)   // 197632 B
#define STAGE_TX (A_STAGE + B_STAGE)              // 49152

// ---------------------------------------------------------------------------
// Device scratch
// ---------------------------------------------------------------------------
__device__ __align__(1024) int8_t g_xq[(size_t)M_TOTAL * K_TOTAL]; // [M][K]
__device__ __align__(1024) int8_t g_kq[(size_t)N_TOTAL * K_TOTAL]; // [N][K] (W^T)
__device__ float g_sx[M_TOTAL];
__device__ float g_sk[N_TOTAL];
__device__ float g_kpart[16 * N_TOTAL];

// ---------------------------------------------------------------------------
// Helpers
// ---------------------------------------------------------------------------
__device__ __forceinline__ uint32_t smem_u32(const void* p) {
    uint32_t a;
    asm("{ .reg .u64 t; cvta.to.shared.u64 t, %1; cvt.u32.u64 %0, t; }" : "=r"(a) : "l"(p));
    return a;
}
__device__ __forceinline__ void mbar_init(uint32_t a, uint32_t cnt) {
    asm volatile("mbarrier.init.shared.b64 [%0], %1;" :: "r"(a), "r"(cnt) : "memory");
}
__device__ __forceinline__ void mbar_expect_tx(uint32_t a, uint32_t bytes) {
    asm volatile("mbarrier.arrive.expect_tx.shared.b64 _, [%0], %1;" :: "r"(a), "r"(bytes) : "memory");
}
__device__ __forceinline__ void mbar_wait(uint32_t a, uint32_t parity) {
    asm volatile(
        "{\n\t.reg .pred P;\n"
        "W%=:\n\t"
        "mbarrier.try_wait.parity.acquire.cta.shared::cta.b64 P, [%0], %1, 0x989680;\n\t"
        "@P bra.uni D%=;\n\t"
        "bra.uni W%=;\n"
        "D%=:\n\t}"
        :: "r"(a), "r"(parity) : "memory");
}
__device__ __forceinline__ void tma_2d(uint32_t dst, const void* map, int x, int y, uint32_t bar) {
    asm volatile(
        "cp.async.bulk.tensor.2d.shared::cta.global.tile.mbarrier::complete_tx::bytes "
        "[%0], [%1, {%2, %3}], [%4];"
        :: "r"(dst), "l"(map), "r"(x), "r"(y), "r"(bar) : "memory");
}
__device__ __forceinline__ void ldsm_x4(uint32_t* r, uint32_t addr) {
    asm volatile("ldmatrix.sync.aligned.m8n8.x4.shared.b16 {%0,%1,%2,%3}, [%4];"
                 : "=r"(r[0]), "=r"(r[1]), "=r"(r[2]), "=r"(r[3]) : "r"(addr));
}
__device__ __forceinline__ void mma_s8(int* d, const uint32_t* a, const uint32_t* b) {
    asm volatile(
        "mma.sync.aligned.m16n8k32.row.col.s32.s8.s8.s32 "
        "{%0,%1,%2,%3}, {%4,%5,%6,%7}, {%8,%9}, {%0,%1,%2,%3};"
        : "+r"(d[0]), "+r"(d[1]), "+r"(d[2]), "+r"(d[3])
        : "r"(a[0]), "r"(a[1]), "r"(a[2]), "r"(a[3]), "r"(b[0]), "r"(b[1]));
}
__device__ __forceinline__ void lds128(uint32_t* r, uint32_t addr) {
    asm volatile("ld.shared.v4.u32 {%0,%1,%2,%3}, [%4];"
                 : "=r"(r[0]), "=r"(r[1]), "=r"(r[2]), "=r"(r[3]) : "r"(addr));
}
__device__ __forceinline__ int dp4a_s32(uint32_t a, uint32_t b, int c) {
    int d;
    asm("dp4a.s32.s32 %0, %1, %2, %3;" : "=r"(d) : "r"(a), "r"(b), "r"(c));
    return d;
}

// ---------------------------------------------------------------------------
// Pre-pass 1: per-row dynamic int8 quant of X -> g_xq, g_sx
// ---------------------------------------------------------------------------
__global__ void quant_x_kernel(const float* __restrict__ x) {
    const int m = blockIdx.x;
    const int t = threadIdx.x;  // 256 threads
    const float4* row = reinterpret_cast<const float4*>(x + (size_t)m * K_TOTAL);
    float4 v[4];
    float amax = 0.f;
#pragma unroll
    for (int i = 0; i < 4; i++) {
        v[i] = row[t + i * 256];
        amax = fmaxf(amax, fmaxf(fmaxf(fabsf(v[i].x), fabsf(v[i].y)),
                                 fmaxf(fabsf(v[i].z), fabsf(v[i].w))));
    }
#pragma unroll
    for (int o = 16; o > 0; o >>= 1) amax = fmaxf(amax, __shfl_xor_sync(0xffffffffu, amax, o));
    __shared__ float red[8];
    __shared__ float s_scale;
    if ((t & 31) == 0) red[t >> 5] = amax;
    __syncthreads();
    if (t < 32) {
        float a = (t < 8) ? red[t] : 0.f;
#pragma unroll
        for (int o = 4; o > 0; o >>= 1) a = fmaxf(a, __shfl_xor_sync(0xffffffffu, a, o));
        if (t == 0) {
            float s = fmaxf(a, 1e-6f) / 127.0f;
            s_scale = s;
            g_sx[m] = s;
        }
    }
    __syncthreads();
    const float inv = 1.0f / s_scale;
    uint32_t* outp = reinterpret_cast<uint32_t*>(g_xq + (size_t)m * K_TOTAL);
#pragma unroll
    for (int i = 0; i < 4; i++) {
        int q0 = (int)fminf(fmaxf(rintf(v[i].x * inv), -127.f), 127.f);
        int q1 = (int)fminf(fmaxf(rintf(v[i].y * inv), -127.f), 127.f);
        int q2 = (int)fminf(fmaxf(rintf(v[i].z * inv), -127.f), 127.f);
        int q3 = (int)fminf(fmaxf(rintf(v[i].w * inv), -127.f), 127.f);
        outp[t + i * 256] = (uint32_t)(q0 & 0xFF) | ((uint32_t)(q1 & 0xFF) << 8) |
                            ((uint32_t)(q2 & 0xFF) << 16) | ((uint32_t)q3 << 24);
    }
}

// ---------------------------------------------------------------------------
// Pre-pass 2: partial column amax of W [K, N] (float4: 4 cols/thread)
// ---------------------------------------------------------------------------
__global__ void k_amax_partial_kernel(const float* __restrict__ kern) {
    const int f4 = blockIdx.x * 1024 + threadIdx.x * 4;
    const int d0 = blockIdx.y * 256;
    float4 a = {0.f, 0.f, 0.f, 0.f};
#pragma unroll 4
    for (int d = d0; d < d0 + 256; d++) {
        float4 v = *reinterpret_cast<const float4*>(kern + (size_t)d * N_TOTAL + f4);
        a.x = fmaxf(a.x, fabsf(v.x));
        a.y = fmaxf(a.y, fabsf(v.y));
        a.z = fmaxf(a.z, fabsf(v.z));
        a.w = fmaxf(a.w, fabsf(v.w));
    }
    *reinterpret_cast<float4*>(&g_kpart[blockIdx.y * N_TOTAL + f4]) = a;
}

// ---------------------------------------------------------------------------
// Pre-pass 3: reduce partials -> sk, quantize W, transpose to [N][K] int8
// ---------------------------------------------------------------------------
__global__ void k_quant_fused_kernel(const float* __restrict__ kern) {
    __shared__ float tile[32][33];
    __shared__ float s_inv[32];
    const int f0 = blockIdx.x * 32;
    const int d0 = blockIdx.y * 32;
    const int tx = threadIdx.x, ty = threadIdx.y;  // (32, 8)
    if (ty == 0) {
        float a = 0.f;
#pragma unroll
        for (int p = 0; p < 16; p++) a = fmaxf(a, g_kpart[p * N_TOTAL + f0 + tx]);
        float s = fmaxf(a, 1e-6f) / 127.0f;
        s_inv[tx] = 1.0f / s;
        if (blockIdx.y == 0) g_sk[f0 + tx] = s;
    }
    __syncthreads();
    const float inv = s_inv[tx];
#pragma unroll
    for (int r = 0; r < 32; r += 8) {
        float q = fminf(fmaxf(rintf(kern[(size_t)(d0 + ty + r) * N_TOTAL + (f0 + tx)] * inv),
                              -127.f), 127.f);
        tile[ty + r][tx] = q;
    }
    __syncthreads();
#pragma unroll
    for (int r = 0; r < 32; r += 8) {
        g_kq[(size_t)(f0 + ty + r) * K_TOTAL + (d0 + tx)] = (int8_t)tile[tx][ty + r];
    }
}

// ---------------------------------------------------------------------------
// Hybrid GEMM v8: warps 0-7 IMMA over N[0,128); warps 8-15 dp4a over N[128,256)
// ---------------------------------------------------------------------------
__global__ void __launch_bounds__(NTHREADS, 1) gemm_s8_kernel(
    const __grid_constant__ CUtensorMap tmap_a,
    const __grid_constant__ CUtensorMap tmap_b,
    float* __restrict__ out)
{
    extern __shared__ char smem[];
    const uint32_t sb = smem_u32(smem);

    const int tid = threadIdx.x;
    const int wid = tid >> 5;
    const int lane = tid & 31;
    const int n0 = blockIdx.x * BN;
    const int m0 = blockIdx.y * BM;

    if (tid == 0) {
#pragma unroll
        for (int s = 0; s < STAGES; s++) mbar_init(sb + s * 16, 1);
    }
    __syncthreads();

    if (tid == 0) {
#pragma unroll
        for (int p = 0; p < STAGES - 1; p++) {
            mbar_expect_tx(sb + p * 16, STAGE_TX);
            tma_2d(sb + SMEM_A0 + p * A_STAGE, &tmap_a, p * BK, m0, sb + p * 16);
            tma_2d(sb + SMEM_B0 + p * B_STAGE, &tmap_b, p * BK, n0, sb + p * 16);
        }
    }

    // ---- tensor-warp state (wid 0..7): warp tile 64x32 over N[0,128) ----
    const int warp_m = wid & 1;
    const int warp_n = wid >> 1;         // 0..3
    const int arow = warp_m * 64 + ((lane >> 3) & 1) * 8 + (lane & 7);
    const int acsel = (lane >> 4) & 1;
    const int brow = warp_n * 32 + ((lane >> 4) & 1) * 8 + (lane & 7);
    const int bcsel = (lane >> 3) & 1;
    const int swl = lane & 7;
    // XOR identity: ((2w+sel)^swl)<<4 == ((sel^swl)<<4) ^ (w<<5)
    uint32_t aAddr0[4], bAddr0[2];
#pragma unroll
    for (int mb = 0; mb < 4; mb++)
        aAddr0[mb] = (uint32_t)(arow + mb * 16) * BK + (uint32_t)((acsel ^ swl) << 4);
#pragma unroll
    for (int g = 0; g < 2; g++)
        bAddr0[g] = (uint32_t)(brow + g * 16) * BK + (uint32_t)((bcsel ^ swl) << 4);

    int acc[4][4][4];
#pragma unroll
    for (int mb = 0; mb < 4; mb++)
#pragma unroll
        for (int nb = 0; nb < 4; nb++)
#pragma unroll
            for (int r = 0; r < 4; r++) acc[mb][nb][r] = 0;

    // ---- dp4a-warp state (wid 8..15): warp tile 32x64 over N[128,256) ----
    const int widD = wid - 8;
    const int wmD = widD & 3;
    const int wnD = widD >> 2;
    const int tmD = lane >> 3;           // 0..3
    const int tnD = lane & 7;            // 0..7
    // A bases WITHOUT chunk bits (bits 4-6 of m*BK are zero): enables
    // immediate-offset LDS per physical chunk in the p-loop below.
    uint32_t aBase[8], bOff[8];
#pragma unroll
    for (int i = 0; i < 8; i++) {
        int m = wmD * 32 + tmD + 4 * i;  // m&7 = tmD ^ (4*(i&1))
        aBase[i] = (uint32_t)m * BK;
    }
#pragma unroll
    for (int j = 0; j < 8; j++) {
        int n = BN_T + wnD * 64 + tnD + 8 * j;   // n&7 == tnD
        bOff[j] = (uint32_t)n * BK + (uint32_t)((n & 7) << 4);
    }
    const uint32_t tmx = (uint32_t)(tmD << 4);
    int accD[8][8];
#pragma unroll
    for (int i = 0; i < 8; i++)
#pragma unroll
        for (int j = 0; j < 8; j++) accD[i][j] = 0;

    for (int kt = 0; kt < KITERS; kt++) {
        if (tid == 0 && kt + STAGES - 1 < KITERS) {
            const int ps = (kt + STAGES - 1) & (STAGES - 1);
            mbar_expect_tx(sb + ps * 16, STAGE_TX);
            tma_2d(sb + SMEM_A0 + ps * A_STAGE, &tmap_a, (kt + STAGES - 1) * BK, m0,
                   sb + ps * 16);
            tma_2d(sb + SMEM_B0 + ps * B_STAGE, &tmap_b, (kt + STAGES - 1) * BK, n0,
                   sb + ps * 16);
        }

        const int st = kt & (STAGES - 1);
        mbar_wait(sb + st * 16, (kt >> 2) & 1);

        const uint32_t aSt = sb + SMEM_A0 + st * A_STAGE;
        const uint32_t bSt = sb + SMEM_B0 + st * B_STAGE;

        if (tid < 256) {
            // -------- IMMA path: 4 x k32 steps, 64x32 per warp --------
#pragma unroll
            for (int w = 0; w < 4; w++) {
                uint32_t afr[4][4], bfr[4][2];
#pragma unroll
                for (int mb = 0; mb < 4; mb++)
                    ldsm_x4(afr[mb], (aSt + aAddr0[mb]) ^ (uint32_t)(w << 5));
#pragma unroll
                for (int g = 0; g < 2; g++) {
                    uint32_t r[4];
                    ldsm_x4(r, (bSt + bAddr0[g]) ^ (uint32_t)(w << 5));
                    bfr[2 * g][0] = r[0]; bfr[2 * g][1] = r[1];
                    bfr[2 * g + 1][0] = r[2]; bfr[2 * g + 1][1] = r[3];
                }
#pragma unroll
                for (int mb = 0; mb < 4; mb++)
#pragma unroll
                    for (int nb = 0; nb < 4; nb++)
                        mma_s8(acc[mb][nb], afr[mb], bfr[nb]);
            }
        } else {
            // -------- dp4a path: per-thread chunk order c = p ^ tmD ----------
            // A physical chunk = c ^ (m&7) = p ^ (4*(i&1))  -> COMPILE-TIME
            // B physical chunk = c ^ tnD -> addr = (bSt+bOff[j]) ^ cx (runtime)
#pragma unroll
            for (int p = 0; p < 8; p++) {
                const uint32_t cx = (uint32_t)(p << 4) ^ tmx;  // (c<<4), c = p^tmD
                uint32_t av[8][4];
#pragma unroll
                for (int i = 0; i < 8; i++)
                    lds128(av[i], aSt + aBase[i] +
                                  (uint32_t)(((p ^ ((i & 1) << 2)) << 4)));
#pragma unroll
                for (int jj = 0; jj < 2; jj++) {
                    uint32_t bv[4][4];
#pragma unroll
                    for (int j4 = 0; j4 < 4; j4++)
                        lds128(bv[j4], (bSt + bOff[jj * 4 + j4]) ^ cx);
#pragma unroll
                    for (int i = 0; i < 8; i++)
#pragma unroll
                        for (int j4 = 0; j4 < 4; j4++)
#pragma unroll
                            for (int w = 0; w < 4; w++)
                                accD[i][jj * 4 + j4] =
                                    dp4a_s32(av[i][w], bv[j4][w], accD[i][jj * 4 + j4]);
                }
            }
        }

        __syncthreads();   // release stage st for the producer
    }

    // ---------------- Epilogue ----------------
    if (tid < 256) {
        const int qid = lane >> 2;
        const int qtid = lane & 3;
#pragma unroll
        for (int mb = 0; mb < 4; mb++) {
            const int mlo = m0 + warp_m * 64 + mb * 16 + qid;
            const float sx0 = g_sx[mlo];
            const float sx1 = g_sx[mlo + 8];
            float* orow0 = out + (size_t)mlo * N_TOTAL + n0;
            float* orow1 = out + (size_t)(mlo + 8) * N_TOTAL + n0;
#pragma unroll
            for (int nb = 0; nb < 4; nb++) {
                const int n = warp_n * 32 + nb * 8 + qtid * 2;
                const float k0v = g_sk[n0 + n], k1v = g_sk[n0 + n + 1];
                float2 r0, r1;
                r0.x = (float)acc[mb][nb][0] * sx0 * k0v;
                r0.y = (float)acc[mb][nb][1] * sx0 * k1v;
                r1.x = (float)acc[mb][nb][2] * sx1 * k0v;
                r1.y = (float)acc[mb][nb][3] * sx1 * k1v;
                *reinterpret_cast<float2*>(orow0 + n) = r0;
                *reinterpret_cast<float2*>(orow1 + n) = r1;
            }
        }
    } else {
#pragma unroll
        for (int i = 0; i < 8; i++) {
            const int m = m0 + wmD * 32 + tmD + 4 * i;
            const float sx = g_sx[m];
            float* orow = out + (size_t)m * N_TOTAL + n0;
#pragma unroll
            for (int j = 0; j < 8; j++) {
                const int n = BN_T + wnD * 64 + tnD + 8 * j;
                orow[n] = (float)accD[i][j] * sx * g_sk[n0 + n];
            }
        }
    }
}

// ---------------------------------------------------------------------------
// Launch (GEMM at global launch index 5 so ncu -s 5 profiles it)
// ---------------------------------------------------------------------------
typedef CUresult (*PFN_encode_t)(CUtensorMap*, CUtensorMapDataType, cuuint32_t, void*,
                                 const cuuint64_t*, const cuuint64_t*, const cuuint32_t*,
                                 const cuuint32_t*, CUtensorMapInterleave, CUtensorMapSwizzle,
                                 CUtensorMapL2promotion, CUtensorMapFloatOOBfill);

extern "C" void kernel_launch(void* const* d_in, const int* in_sizes, int n_in,
                              void* d_out, int out_size) {
    const float* x = (const float*)d_in[0];
    const float* kern = (const float*)d_in[1];
    if (n_in >= 2 && in_sizes[0] < in_sizes[1]) {
        const float* t = x; x = kern; kern = t;
    }
    float* out = (float*)d_out;

    quant_x_kernel<<<M_TOTAL, 256>>>(x);
    k_amax_partial_kernel<<<dim3(N_TOTAL / 1024, K_TOTAL / 256), 256>>>(kern);
    k_quant_fused_kernel<<<dim3(N_TOTAL / 32, K_TOTAL / 32), dim3(32, 8)>>>(kern);

    void* xq_ptr = nullptr;
    void* kq_ptr = nullptr;
    cudaGetSymbolAddress(&xq_ptr, g_xq);
    cudaGetSymbolAddress(&kq_ptr, g_kq);

    void* fnp = nullptr;
    cudaDriverEntryPointQueryResult qr;
    cudaGetDriverEntryPointByVersion("cuTensorMapEncodeTiled", &fnp, 12000,
                                     cudaEnableDefault, &qr);
    PFN_encode_t encode = (PFN_encode_t)fnp;

    CUtensorMap tA, tB;
    {
        cuuint64_t dims[2] = {K_TOTAL, M_TOTAL};
        cuuint64_t str[1] = {K_TOTAL};
        cuuint32_t box[2] = {BK, BM};
        cuuint32_t es[2] = {1, 1};
        encode(&tA, CU_TENSOR_MAP_DATA_TYPE_UINT8, 2, xq_ptr, dims, str, box, es,
               CU_TENSOR_MAP_INTERLEAVE_NONE, CU_TENSOR_MAP_SWIZZLE_128B,
               CU_TENSOR_MAP_L2_PROMOTION_L2_128B, CU_TENSOR_MAP_FLOAT_OOB_FILL_NONE);
    }
    {
        cuuint64_t dims[2] = {K_TOTAL, N_TOTAL};
        cuuint64_t str[1] = {K_TOTAL};
        cuuint32_t box[2] = {BK, BN};
        cuuint32_t es[2] = {1, 1};
        encode(&tB, CU_TENSOR_MAP_DATA_TYPE_UINT8, 2, kq_ptr, dims, str, box, es,
               CU_TENSOR_MAP_INTERLEAVE_NONE, CU_TENSOR_MAP_SWIZZLE_128B,
               CU_TENSOR_MAP_L2_PROMOTION_L2_128B, CU_TENSOR_MAP_FLOAT_OOB_FILL_NONE);
    }

    cudaFuncSetAttribute(gemm_s8_kernel, cudaFuncAttributeMaxDynamicSharedMemorySize,
                         SMEM_TOTAL);
    gemm_s8_kernel<<<dim3(N_TOTAL / BN, M_TOTAL / BM), NTHREADS, SMEM_TOTAL>>>(tA, tB, out);
}

// round 16
// speedup vs baseline: 1.3661x; 1.0111x over previous
#include <cuda_runtime.h>
#include <cuda.h>
#include <cuda_bf16.h>
#include <cstdint>

// ---------------------------------------------------------------------------
// Problem dims
// ---------------------------------------------------------------------------
#define M_TOTAL 8192
#define N_TOTAL 4096
#define K_TOTAL 4096

// Hybrid GEMM v8 (R15, best=1458us): 8 IMMA warps N[0,128) + 8 dp4a warps
// N[128,256), TMA loads, 4 stages, dp4a A-operands via immediate offsets.
// R16: GEMM frozen; fix k_amax_partial occupancy (64 -> 128 blocks, unroll 8).
#define BM 128
#define BN 256
#define BK 128
#define STAGES 4
#define KITERS (K_TOTAL / BK)       // 32

#define BN_T 128                    // tensor columns  N[0,128)
#define NTHREADS 512

#define KPARTS 32                   // column-amax partials (was 16)

#define A_STAGE (BM * BK)           // 16384 B
#define B_STAGE (BN * BK)           // 32768 B
#define CTRL_BYTES 1024
#define SMEM_A0 CTRL_BYTES
#define SMEM_B0 (SMEM_A0 + STAGES * A_STAGE)
#define SMEM_TOTAL (SMEM_B0 + STAGES * B_STAGE)   // 197632 B
#define STAGE_TX (A_STAGE + B_STAGE)              // 49152

// ---------------------------------------------------------------------------
// Device scratch
// ---------------------------------------------------------------------------
__device__ __align__(1024) int8_t g_xq[(size_t)M_TOTAL * K_TOTAL]; // [M][K]
__device__ __align__(1024) int8_t g_kq[(size_t)N_TOTAL * K_TOTAL]; // [N][K] (W^T)
__device__ float g_sx[M_TOTAL];
__device__ float g_sk[N_TOTAL];
__device__ float g_kpart[KPARTS * N_TOTAL];

// ---------------------------------------------------------------------------
// Helpers
// ---------------------------------------------------------------------------
__device__ __forceinline__ uint32_t smem_u32(const void* p) {
    uint32_t a;
    asm("{ .reg .u64 t; cvta.to.shared.u64 t, %1; cvt.u32.u64 %0, t; }" : "=r"(a) : "l"(p));
    return a;
}
__device__ __forceinline__ void mbar_init(uint32_t a, uint32_t cnt) {
    asm volatile("mbarrier.init.shared.b64 [%0], %1;" :: "r"(a), "r"(cnt) : "memory");
}
__device__ __forceinline__ void mbar_expect_tx(uint32_t a, uint32_t bytes) {
    asm volatile("mbarrier.arrive.expect_tx.shared.b64 _, [%0], %1;" :: "r"(a), "r"(bytes) : "memory");
}
__device__ __forceinline__ void mbar_wait(uint32_t a, uint32_t parity) {
    asm volatile(
        "{\n\t.reg .pred P;\n"
        "W%=:\n\t"
        "mbarrier.try_wait.parity.acquire.cta.shared::cta.b64 P, [%0], %1, 0x989680;\n\t"
        "@P bra.uni D%=;\n\t"
        "bra.uni W%=;\n"
        "D%=:\n\t}"
        :: "r"(a), "r"(parity) : "memory");
}
__device__ __forceinline__ void tma_2d(uint32_t dst, const void* map, int x, int y, uint32_t bar) {
    asm volatile(
        "cp.async.bulk.tensor.2d.shared::cta.global.tile.mbarrier::complete_tx::bytes "
        "[%0], [%1, {%2, %3}], [%4];"
        :: "r"(dst), "l"(map), "r"(x), "r"(y), "r"(bar) : "memory");
}
__device__ __forceinline__ void ldsm_x4(uint32_t* r, uint32_t addr) {
    asm volatile("ldmatrix.sync.aligned.m8n8.x4.shared.b16 {%0,%1,%2,%3}, [%4];"
                 : "=r"(r[0]), "=r"(r[1]), "=r"(r[2]), "=r"(r[3]) : "r"(addr));
}
__device__ __forceinline__ void mma_s8(int* d, const uint32_t* a, const uint32_t* b) {
    asm volatile(
        "mma.sync.aligned.m16n8k32.row.col.s32.s8.s8.s32 "
        "{%0,%1,%2,%3}, {%4,%5,%6,%7}, {%8,%9}, {%0,%1,%2,%3};"
        : "+r"(d[0]), "+r"(d[1]), "+r"(d[2]), "+r"(d[3])
        : "r"(a[0]), "r"(a[1]), "r"(a[2]), "r"(a[3]), "r"(b[0]), "r"(b[1]));
}
__device__ __forceinline__ void lds128(uint32_t* r, uint32_t addr) {
    asm volatile("ld.shared.v4.u32 {%0,%1,%2,%3}, [%4];"
                 : "=r"(r[0]), "=r"(r[1]), "=r"(r[2]), "=r"(r[3]) : "r"(addr));
}
__device__ __forceinline__ int dp4a_s32(uint32_t a, uint32_t b, int c) {
    int d;
    asm("dp4a.s32.s32 %0, %1, %2, %3;" : "=r"(d) : "r"(a), "r"(b), "r"(c));
    return d;
}

// ---------------------------------------------------------------------------
// Pre-pass 1: per-row dynamic int8 quant of X -> g_xq, g_sx
// ---------------------------------------------------------------------------
__global__ void quant_x_kernel(const float* __restrict__ x) {
    const int m = blockIdx.x;
    const int t = threadIdx.x;  // 256 threads
    const float4* row = reinterpret_cast<const float4*>(x + (size_t)m * K_TOTAL);
    float4 v[4];
    float amax = 0.f;
#pragma unroll
    for (int i = 0; i < 4; i++) {
        v[i] = row[t + i * 256];
        amax = fmaxf(amax, fmaxf(fmaxf(fabsf(v[i].x), fabsf(v[i].y)),
                                 fmaxf(fabsf(v[i].z), fabsf(v[i].w))));
    }
#pragma unroll
    for (int o = 16; o > 0; o >>= 1) amax = fmaxf(amax, __shfl_xor_sync(0xffffffffu, amax, o));
    __shared__ float red[8];
    __shared__ float s_scale;
    if ((t & 31) == 0) red[t >> 5] = amax;
    __syncthreads();
    if (t < 32) {
        float a = (t < 8) ? red[t] : 0.f;
#pragma unroll
        for (int o = 4; o > 0; o >>= 1) a = fmaxf(a, __shfl_xor_sync(0xffffffffu, a, o));
        if (t == 0) {
            float s = fmaxf(a, 1e-6f) / 127.0f;
            s_scale = s;
            g_sx[m] = s;
        }
    }
    __syncthreads();
    const float inv = 1.0f / s_scale;
    uint32_t* outp = reinterpret_cast<uint32_t*>(g_xq + (size_t)m * K_TOTAL);
#pragma unroll
    for (int i = 0; i < 4; i++) {
        int q0 = (int)fminf(fmaxf(rintf(v[i].x * inv), -127.f), 127.f);
        int q1 = (int)fminf(fmaxf(rintf(v[i].y * inv), -127.f), 127.f);
        int q2 = (int)fminf(fmaxf(rintf(v[i].z * inv), -127.f), 127.f);
        int q3 = (int)fminf(fmaxf(rintf(v[i].w * inv), -127.f), 127.f);
        outp[t + i * 256] = (uint32_t)(q0 & 0xFF) | ((uint32_t)(q1 & 0xFF) << 8) |
                            ((uint32_t)(q2 & 0xFF) << 16) | ((uint32_t)q3 << 24);
    }
}

// ---------------------------------------------------------------------------
// Pre-pass 2: partial column amax of W [K, N]
// grid (4, 32) = 128 blocks (covers the chip; old 4x16=64 left SMs idle),
// 128 k-rows per block, float4 columns, unroll 8 for MLP.
// ---------------------------------------------------------------------------
__global__ void k_amax_partial_kernel(const float* __restrict__ kern) {
    const int f4 = blockIdx.x * 1024 + threadIdx.x * 4;
    const int d0 = blockIdx.y * (K_TOTAL / KPARTS);   // 128 rows
    float4 a = {0.f, 0.f, 0.f, 0.f};
#pragma unroll 8
    for (int d = d0; d < d0 + (K_TOTAL / KPARTS); d++) {
        float4 v = *reinterpret_cast<const float4*>(kern + (size_t)d * N_TOTAL + f4);
        a.x = fmaxf(a.x, fabsf(v.x));
        a.y = fmaxf(a.y, fabsf(v.y));
        a.z = fmaxf(a.z, fabsf(v.z));
        a.w = fmaxf(a.w, fabsf(v.w));
    }
    *reinterpret_cast<float4*>(&g_kpart[blockIdx.y * N_TOTAL + f4]) = a;
}

// ---------------------------------------------------------------------------
// Pre-pass 3: reduce partials -> sk, quantize W, transpose to [N][K] int8
// ---------------------------------------------------------------------------
__global__ void k_quant_fused_kernel(const float* __restrict__ kern) {
    __shared__ float tile[32][33];
    __shared__ float s_inv[32];
    const int f0 = blockIdx.x * 32;
    const int d0 = blockIdx.y * 32;
    const int tx = threadIdx.x, ty = threadIdx.y;  // (32, 8)
    if (ty == 0) {
        float a = 0.f;
#pragma unroll
        for (int p = 0; p < KPARTS; p++) a = fmaxf(a, g_kpart[p * N_TOTAL + f0 + tx]);
        float s = fmaxf(a, 1e-6f) / 127.0f;
        s_inv[tx] = 1.0f / s;
        if (blockIdx.y == 0) g_sk[f0 + tx] = s;
    }
    __syncthreads();
    const float inv = s_inv[tx];
#pragma unroll
    for (int r = 0; r < 32; r += 8) {
        float q = fminf(fmaxf(rintf(kern[(size_t)(d0 + ty + r) * N_TOTAL + (f0 + tx)] * inv),
                              -127.f), 127.f);
        tile[ty + r][tx] = q;
    }
    __syncthreads();
#pragma unroll
    for (int r = 0; r < 32; r += 8) {
        g_kq[(size_t)(f0 + ty + r) * K_TOTAL + (d0 + tx)] = (int8_t)tile[tx][ty + r];
    }
}

// ---------------------------------------------------------------------------
// Hybrid GEMM v8: warps 0-7 IMMA over N[0,128); warps 8-15 dp4a over N[128,256)
// ---------------------------------------------------------------------------
__global__ void __launch_bounds__(NTHREADS, 1) gemm_s8_kernel(
    const __grid_constant__ CUtensorMap tmap_a,
    const __grid_constant__ CUtensorMap tmap_b,
    float* __restrict__ out)
{
    extern __shared__ char smem[];
    const uint32_t sb = smem_u32(smem);

    const int tid = threadIdx.x;
    const int wid = tid >> 5;
    const int lane = tid & 31;
    const int n0 = blockIdx.x * BN;
    const int m0 = blockIdx.y * BM;

    if (tid == 0) {
#pragma unroll
        for (int s = 0; s < STAGES; s++) mbar_init(sb + s * 16, 1);
    }
    __syncthreads();

    if (tid == 0) {
#pragma unroll
        for (int p = 0; p < STAGES - 1; p++) {
            mbar_expect_tx(sb + p * 16, STAGE_TX);
            tma_2d(sb + SMEM_A0 + p * A_STAGE, &tmap_a, p * BK, m0, sb + p * 16);
            tma_2d(sb + SMEM_B0 + p * B_STAGE, &tmap_b, p * BK, n0, sb + p * 16);
        }
    }

    // ---- tensor-warp state (wid 0..7): warp tile 64x32 over N[0,128) ----
    const int warp_m = wid & 1;
    const int warp_n = wid >> 1;         // 0..3
    const int arow = warp_m * 64 + ((lane >> 3) & 1) * 8 + (lane & 7);
    const int acsel = (lane >> 4) & 1;
    const int brow = warp_n * 32 + ((lane >> 4) & 1) * 8 + (lane & 7);
    const int bcsel = (lane >> 3) & 1;
    const int swl = lane & 7;
    // XOR identity: ((2w+sel)^swl)<<4 == ((sel^swl)<<4) ^ (w<<5)
    uint32_t aAddr0[4], bAddr0[2];
#pragma unroll
    for (int mb = 0; mb < 4; mb++)
        aAddr0[mb] = (uint32_t)(arow + mb * 16) * BK + (uint32_t)((acsel ^ swl) << 4);
#pragma unroll
    for (int g = 0; g < 2; g++)
        bAddr0[g] = (uint32_t)(brow + g * 16) * BK + (uint32_t)((bcsel ^ swl) << 4);

    int acc[4][4][4];
#pragma unroll
    for (int mb = 0; mb < 4; mb++)
#pragma unroll
        for (int nb = 0; nb < 4; nb++)
#pragma unroll
            for (int r = 0; r < 4; r++) acc[mb][nb][r] = 0;

    // ---- dp4a-warp state (wid 8..15): warp tile 32x64 over N[128,256) ----
    const int widD = wid - 8;
    const int wmD = widD & 3;
    const int wnD = widD >> 2;
    const int tmD = lane >> 3;           // 0..3
    const int tnD = lane & 7;            // 0..7
    // A bases WITHOUT chunk bits (bits 4-6 of m*BK are zero): enables
    // immediate-offset LDS per physical chunk in the p-loop below.
    uint32_t aBase[8], bOff[8];
#pragma unroll
    for (int i = 0; i < 8; i++) {
        int m = wmD * 32 + tmD + 4 * i;  // m&7 = tmD ^ (4*(i&1))
        aBase[i] = (uint32_t)m * BK;
    }
#pragma unroll
    for (int j = 0; j < 8; j++) {
        int n = BN_T + wnD * 64 + tnD + 8 * j;   // n&7 == tnD
        bOff[j] = (uint32_t)n * BK + (uint32_t)((n & 7) << 4);
    }
    const uint32_t tmx = (uint32_t)(tmD << 4);
    int accD[8][8];
#pragma unroll
    for (int i = 0; i < 8; i++)
#pragma unroll
        for (int j = 0; j < 8; j++) accD[i][j] = 0;

    for (int kt = 0; kt < KITERS; kt++) {
        if (tid == 0 && kt + STAGES - 1 < KITERS) {
            const int ps = (kt + STAGES - 1) & (STAGES - 1);
            mbar_expect_tx(sb + ps * 16, STAGE_TX);
            tma_2d(sb + SMEM_A0 + ps * A_STAGE, &tmap_a, (kt + STAGES - 1) * BK, m0,
                   sb + ps * 16);
            tma_2d(sb + SMEM_B0 + ps * B_STAGE, &tmap_b, (kt + STAGES - 1) * BK, n0,
                   sb + ps * 16);
        }

        const int st = kt & (STAGES - 1);
        mbar_wait(sb + st * 16, (kt >> 2) & 1);

        const uint32_t aSt = sb + SMEM_A0 + st * A_STAGE;
        const uint32_t bSt = sb + SMEM_B0 + st * B_STAGE;

        if (tid < 256) {
            // -------- IMMA path: 4 x k32 steps, 64x32 per warp --------
#pragma unroll
            for (int w = 0; w < 4; w++) {
                uint32_t afr[4][4], bfr[4][2];
#pragma unroll
                for (int mb = 0; mb < 4; mb++)
                    ldsm_x4(afr[mb], (aSt + aAddr0[mb]) ^ (uint32_t)(w << 5));
#pragma unroll
                for (int g = 0; g < 2; g++) {
                    uint32_t r[4];
                    ldsm_x4(r, (bSt + bAddr0[g]) ^ (uint32_t)(w << 5));
                    bfr[2 * g][0] = r[0]; bfr[2 * g][1] = r[1];
                    bfr[2 * g + 1][0] = r[2]; bfr[2 * g + 1][1] = r[3];
                }
#pragma unroll
                for (int mb = 0; mb < 4; mb++)
#pragma unroll
                    for (int nb = 0; nb < 4; nb++)
                        mma_s8(acc[mb][nb], afr[mb], bfr[nb]);
            }
        } else {
            // -------- dp4a path: per-thread chunk order c = p ^ tmD ----------
            // A physical chunk = c ^ (m&7) = p ^ (4*(i&1))  -> COMPILE-TIME
            // B physical chunk = c ^ tnD -> addr = (bSt+bOff[j]) ^ cx (runtime)
#pragma unroll
            for (int p = 0; p < 8; p++) {
                const uint32_t cx = (uint32_t)(p << 4) ^ tmx;  // (c<<4), c = p^tmD
                uint32_t av[8][4];
#pragma unroll
                for (int i = 0; i < 8; i++)
                    lds128(av[i], aSt + aBase[i] +
                                  (uint32_t)(((p ^ ((i & 1) << 2)) << 4)));
#pragma unroll
                for (int jj = 0; jj < 2; jj++) {
                    uint32_t bv[4][4];
#pragma unroll
                    for (int j4 = 0; j4 < 4; j4++)
                        lds128(bv[j4], (bSt + bOff[jj * 4 + j4]) ^ cx);
#pragma unroll
                    for (int i = 0; i < 8; i++)
#pragma unroll
                        for (int j4 = 0; j4 < 4; j4++)
#pragma unroll
                            for (int w = 0; w < 4; w++)
                                accD[i][jj * 4 + j4] =
                                    dp4a_s32(av[i][w], bv[j4][w], accD[i][jj * 4 + j4]);
                }
            }
        }

        __syncthreads();   // release stage st for the producer
    }

    // ---------------- Epilogue ----------------
    if (tid < 256) {
        const int qid = lane >> 2;
        const int qtid = lane & 3;
#pragma unroll
        for (int mb = 0; mb < 4; mb++) {
            const int mlo = m0 + warp_m * 64 + mb * 16 + qid;
            const float sx0 = g_sx[mlo];
            const float sx1 = g_sx[mlo + 8];
            float* orow0 = out + (size_t)mlo * N_TOTAL + n0;
            float* orow1 = out + (size_t)(mlo + 8) * N_TOTAL + n0;
#pragma unroll
            for (int nb = 0; nb < 4; nb++) {
                const int n = warp_n * 32 + nb * 8 + qtid * 2;
                const float k0v = g_sk[n0 + n], k1v = g_sk[n0 + n + 1];
                float2 r0, r1;
                r0.x = (float)acc[mb][nb][0] * sx0 * k0v;
                r0.y = (float)acc[mb][nb][1] * sx0 * k1v;
                r1.x = (float)acc[mb][nb][2] * sx1 * k0v;
                r1.y = (float)acc[mb][nb][3] * sx1 * k1v;
                *reinterpret_cast<float2*>(orow0 + n) = r0;
                *reinterpret_cast<float2*>(orow1 + n) = r1;
            }
        }
    } else {
#pragma unroll
        for (int i = 0; i < 8; i++) {
            const int m = m0 + wmD * 32 + tmD + 4 * i;
            const float sx = g_sx[m];
            float* orow = out + (size_t)m * N_TOTAL + n0;
#pragma unroll
            for (int j = 0; j < 8; j++) {
                const int n = BN_T + wnD * 64 + tnD + 8 * j;
                orow[n] = (float)accD[i][j] * sx * g_sk[n0 + n];
            }
        }
    }
}

// ---------------------------------------------------------------------------
// Launch (GEMM at global launch index 5 so ncu -s 5 profiles it)
// ---------------------------------------------------------------------------
typedef CUresult (*PFN_encode_t)(CUtensorMap*, CUtensorMapDataType, cuuint32_t, void*,
                                 const cuuint64_t*, const cuuint64_t*, const cuuint32_t*,
                                 const cuuint32_t*, CUtensorMapInterleave, CUtensorMapSwizzle,
                                 CUtensorMapL2promotion, CUtensorMapFloatOOBfill);

extern "C" void kernel_launch(void* const* d_in, const int* in_sizes, int n_in,
                              void* d_out, int out_size) {
    const float* x = (const float*)d_in[0];
    const float* kern = (const float*)d_in[1];
    if (n_in >= 2 && in_sizes[0] < in_sizes[1]) {
        const float* t = x; x = kern; kern = t;
    }
    float* out = (float*)d_out;

    quant_x_kernel<<<M_TOTAL, 256>>>(x);
    k_amax_partial_kernel<<<dim3(N_TOTAL / 1024, KPARTS), 256>>>(kern);
    k_quant_fused_kernel<<<dim3(N_TOTAL / 32, K_TOTAL / 32), dim3(32, 8)>>>(kern);

    void* xq_ptr = nullptr;
    void* kq_ptr = nullptr;
    cudaGetSymbolAddress(&xq_ptr, g_xq);
    cudaGetSymbolAddress(&kq_ptr, g_kq);

    void* fnp = nullptr;
    cudaDriverEntryPointQueryResult qr;
    cudaGetDriverEntryPointByVersion("cuTensorMapEncodeTiled", &fnp, 12000,
                                     cudaEnableDefault, &qr);
    PFN_encode_t encode = (PFN_encode_t)fnp;

    CUtensorMap tA, tB;
    {
        cuuint64_t dims[2] = {K_TOTAL, M_TOTAL};
        cuuint64_t str[1] = {K_TOTAL};
        cuuint32_t box[2] = {BK, BM};
        cuuint32_t es[2] = {1, 1};
        encode(&tA, CU_TENSOR_MAP_DATA_TYPE_UINT8, 2, xq_ptr, dims, str, box, es,
               CU_TENSOR_MAP_INTERLEAVE_NONE, CU_TENSOR_MAP_SWIZZLE_128B,
               CU_TENSOR_MAP_L2_PROMOTION_L2_128B, CU_TENSOR_MAP_FLOAT_OOB_FILL_NONE);
    }
    {
        cuuint64_t dims[2] = {K_TOTAL, N_TOTAL};
        cuuint64_t str[1] = {K_TOTAL};
        cuuint32_t box[2] = {BK, BN};
        cuuint32_t es[2] = {1, 1};
        encode(&tB, CU_TENSOR_MAP_DATA_TYPE_UINT8, 2, kq_ptr, dims, str, box, es,
               CU_TENSOR_MAP_INTERLEAVE_NONE, CU_TENSOR_MAP_SWIZZLE_128B,
               CU_TENSOR_MAP_L2_PROMOTION_L2_128B, CU_TENSOR_MAP_FLOAT_OOB_FILL_NONE);
    }

    cudaFuncSetAttribute(gemm_s8_kernel, cudaFuncAttributeMaxDynamicSharedMemorySize,
                         SMEM_TOTAL);
    gemm_s8_kernel<<<dim3(N_TOTAL / BN, M_TOTAL / BM), NTHREADS, SMEM_TOTAL>>>(tA, tB, out);
}